// round 1
// baseline (speedup 1.0000x reference)
#include <cuda_runtime.h>
#include <math.h>

#define BB 8
#define SS 2048
#define HH 1024
#define DD 64
#define BS (BB*SS)      /* 16384 */
#define QKV_LD 192

#define CLIP_HI 0.9999998807907104f
#define PEXP (-65.5f)

// Scratch (static device allocations are allowed)
__device__ float g_qkv[BS * QKV_LD];     // [row][ q(64) | k(64) | v(64) ]
__device__ float g_colsum[BS];           // [B][S]

// ---------------------------------------------------------------- K0: zero colsum
__global__ void k0_zero() {
    int i = blockIdx.x * blockDim.x + threadIdx.x;
    if (i < BS) g_colsum[i] = 0.0f;
}

// ---------------------------------------------------------------- K1: projections
// qkv_raw[m][which*64+n] = x[m][:] . W[:, n] + b[n]
// BM=128, BN=64, BK=32, 256 threads, 8x4 microtile
__global__ __launch_bounds__(256) void k1_proj(
    const float* __restrict__ x,
    const float* __restrict__ Wq, const float* __restrict__ bq,
    const float* __restrict__ Wk, const float* __restrict__ bk,
    const float* __restrict__ Wv, const float* __restrict__ bv)
{
    __shared__ float xs[32][128 + 4];   // transposed [k][m]
    __shared__ float ws[32][64 + 4];    // [k][n]

    const int which = blockIdx.y;
    const float* W    = (which == 0) ? Wq : ((which == 1) ? Wk : Wv);
    const float* bias = (which == 0) ? bq : ((which == 1) ? bk : bv);
    const int m0 = blockIdx.x * 128;
    const int tid = threadIdx.x;
    const int tx = tid & 15, ty = tid >> 4;

    float acc[8][4];
#pragma unroll
    for (int r = 0; r < 8; r++)
#pragma unroll
        for (int c = 0; c < 4; c++) acc[r][c] = 0.0f;

    for (int k0 = 0; k0 < HH; k0 += 32) {
        // x tile: 128 rows x 32 k  (4096 floats, 4 float4/thread), transposed store
#pragma unroll
        for (int it = 0; it < 4; it++) {
            int f = tid + 256 * it;            // 0..1023 float4 index
            int row = f >> 3;                  // 8 float4 per row
            int dd = (f & 7) * 4;
            float4 v = *(const float4*)(x + (size_t)(m0 + row) * HH + k0 + dd);
            xs[dd + 0][row] = v.x; xs[dd + 1][row] = v.y;
            xs[dd + 2][row] = v.z; xs[dd + 3][row] = v.w;
        }
        // W tile: 32 k x 64 n (2048 floats, 2 float4/thread)
#pragma unroll
        for (int it = 0; it < 2; it++) {
            int f = tid + 256 * it;            // 0..511
            int kr = f >> 4;                   // 16 float4 per k-row
            int nn = (f & 15) * 4;
            *(float4*)&ws[kr][nn] = *(const float4*)(W + (size_t)(k0 + kr) * DD + nn);
        }
        __syncthreads();
#pragma unroll
        for (int kk = 0; kk < 32; kk++) {
            float4 a0 = *(float4*)&xs[kk][ty * 8];
            float4 a1 = *(float4*)&xs[kk][ty * 8 + 4];
            float4 b0 = *(float4*)&ws[kk][tx * 4];
            float a[8] = {a0.x, a0.y, a0.z, a0.w, a1.x, a1.y, a1.z, a1.w};
            float bb[4] = {b0.x, b0.y, b0.z, b0.w};
#pragma unroll
            for (int r = 0; r < 8; r++)
#pragma unroll
                for (int c = 0; c < 4; c++)
                    acc[r][c] = fmaf(a[r], bb[c], acc[r][c]);
        }
        __syncthreads();
    }

    float4 b4 = *(const float4*)(bias + tx * 4);
    float bb[4] = {b4.x, b4.y, b4.z, b4.w};
#pragma unroll
    for (int r = 0; r < 8; r++) {
        float4 o;
        o.x = acc[r][0] + bb[0]; o.y = acc[r][1] + bb[1];
        o.z = acc[r][2] + bb[2]; o.w = acc[r][3] + bb[3];
        *(float4*)(g_qkv + (size_t)(m0 + ty * 8 + r) * QKV_LD + which * 64 + tx * 4) = o;
    }
}

// ---------------------------------------------------------------- K2: L2 normalize
__global__ void k2_norm() {
    int gw = (blockIdx.x * blockDim.x + threadIdx.x) >> 5;
    int lane = threadIdx.x & 31;
    if (gw >= BS * 3) return;
    int row = gw / 3;
    int mat = gw - row * 3;
    float* p = g_qkv + (size_t)row * QKV_LD + mat * 64;
    float2 v = *(float2*)(p + lane * 2);
    float ss = v.x * v.x + v.y * v.y;
#pragma unroll
    for (int o = 16; o; o >>= 1) ss += __shfl_xor_sync(0xFFFFFFFFu, ss, o);
    float inv = 1.0f / fmaxf(sqrtf(ss), 1e-12f);
    v.x *= inv; v.y *= inv;
    *(float2*)(p + lane * 2) = v;
}

// ---------------------------------------------------------------- K3: QK^T -> score, colsums
// per batch, BM=BN=128, 256 threads, 8x8 microtile (2x2 quads of 4x4)
__global__ __launch_bounds__(256) void k3_score(float* __restrict__ probs)
{
    __shared__ float qs[32][128 + 4];   // [d][m]
    __shared__ float ks[32][128 + 4];   // [d][n]
    __shared__ float colred[16][128];

    const int b = blockIdx.z;
    const int m0 = blockIdx.y * 128;
    const int n0 = blockIdx.x * 128;
    const int tid = threadIdx.x;
    const int tx = tid & 15, ty = tid >> 4;

    float acc[8][8];
#pragma unroll
    for (int r = 0; r < 8; r++)
#pragma unroll
        for (int c = 0; c < 8; c++) acc[r][c] = 0.0f;

    for (int d0 = 0; d0 < DD; d0 += 32) {
#pragma unroll
        for (int it = 0; it < 4; it++) {
            int f = tid + 256 * it;       // 0..1023
            int row = f >> 3;
            int dd = (f & 7) * 4;
            float4 vq = *(const float4*)(g_qkv + (size_t)(b * SS + m0 + row) * QKV_LD + d0 + dd);
            qs[dd + 0][row] = vq.x; qs[dd + 1][row] = vq.y;
            qs[dd + 2][row] = vq.z; qs[dd + 3][row] = vq.w;
            float4 vk = *(const float4*)(g_qkv + (size_t)(b * SS + n0 + row) * QKV_LD + 64 + d0 + dd);
            ks[dd + 0][row] = vk.x; ks[dd + 1][row] = vk.y;
            ks[dd + 2][row] = vk.z; ks[dd + 3][row] = vk.w;
        }
        __syncthreads();
#pragma unroll
        for (int dd = 0; dd < 32; dd++) {
            float4 a0 = *(float4*)&qs[dd][ty * 4];
            float4 a1 = *(float4*)&qs[dd][64 + ty * 4];
            float4 b0 = *(float4*)&ks[dd][tx * 4];
            float4 b1 = *(float4*)&ks[dd][64 + tx * 4];
            float a[8]  = {a0.x, a0.y, a0.z, a0.w, a1.x, a1.y, a1.z, a1.w};
            float bbv[8] = {b0.x, b0.y, b0.z, b0.w, b1.x, b1.y, b1.z, b1.w};
#pragma unroll
            for (int r = 0; r < 8; r++)
#pragma unroll
                for (int c = 0; c < 8; c++)
                    acc[r][c] = fmaf(a[r], bbv[c], acc[r][c]);
        }
        __syncthreads();
    }

    // epilogue: clip -> acos -> (1+g)^-65.5 ; write score; column partial sums
    float colpart[8];
#pragma unroll
    for (int c = 0; c < 8; c++) colpart[c] = 0.0f;

    float* pb = probs + (size_t)b * SS * SS;
#pragma unroll
    for (int r = 0; r < 8; r++) {
        int rloc = (r < 4) ? (ty * 4 + r) : (64 + ty * 4 + (r - 4));
#pragma unroll
        for (int c = 0; c < 8; c++) {
            float cosv = acc[r][c];
            cosv = fminf(fmaxf(cosv, -CLIP_HI), CLIP_HI);
            float g = acosf(cosv);
            float sc = __expf(PEXP * __logf(1.0f + g));
            acc[r][c] = sc;
            colpart[c] += sc;
        }
        float* rowp = pb + (size_t)(m0 + rloc) * SS + n0;
        *(float4*)(rowp + tx * 4)      = make_float4(acc[r][0], acc[r][1], acc[r][2], acc[r][3]);
        *(float4*)(rowp + 64 + tx * 4) = make_float4(acc[r][4], acc[r][5], acc[r][6], acc[r][7]);
    }

    __syncthreads();
#pragma unroll
    for (int u = 0; u < 4; u++) {
        colred[ty][tx * 4 + u]      = colpart[u];
        colred[ty][64 + tx * 4 + u] = colpart[4 + u];
    }
    __syncthreads();
    if (tid < 128) {
        float s = 0.0f;
#pragma unroll
        for (int t = 0; t < 16; t++) s += colred[t][tid];
        atomicAdd(&g_colsum[b * SS + n0 + tid], s);
    }
}

// ---------------------------------------------------------------- K4: finalize
// c = colsum^-0.5 ; rowdot_i = sum_j s_ij c_j ; probs = s*c/rowdot ; out = probs@v
// BM=64 rows per block, 256 threads
__global__ __launch_bounds__(256) void k4_final(float* __restrict__ out, float* __restrict__ probs)
{
    __shared__ float c_s[SS];            // 8 KB
    __shared__ float t_s[32][64 + 4];
    __shared__ float v_s[32][64 + 4];
    __shared__ float rdi_s[64];
    __shared__ float red[64][4];

    const int b = blockIdx.y;
    const int i0 = blockIdx.x * 64;
    const int tid = threadIdx.x;
    float* sbase = probs + (size_t)b * SS * SS;

    // phase 0: column scales
    for (int j = tid; j < SS; j += 256)
        c_s[j] = rsqrtf(g_colsum[b * SS + j]);
    __syncthreads();

    // phase 1: rowdot
    {
        int i = tid >> 2;
        int q = tid & 3;
        const float* rp = sbase + (size_t)(i0 + i) * SS + q * 512;
        const float* cp = c_s + q * 512;
        float sum = 0.0f;
        for (int j = 0; j < 512; j += 4) {
            float4 s4 = *(const float4*)(rp + j);
            sum += s4.x * cp[j] + s4.y * cp[j + 1] + s4.z * cp[j + 2] + s4.w * cp[j + 3];
        }
        red[i][q] = sum;
    }
    __syncthreads();
    if (tid < 64) {
        float d = red[tid][0] + red[tid][1] + red[tid][2] + red[tid][3];
        rdi_s[tid] = 1.0f / d;
    }
    __syncthreads();

    const int tx = tid & 15, ty = tid >> 4;
    float acc[4][4];
#pragma unroll
    for (int r = 0; r < 4; r++)
#pragma unroll
        for (int c = 0; c < 4; c++) acc[r][c] = 0.0f;

    for (int j0 = 0; j0 < SS; j0 += 32) {
        // load v chunk 32x64
#pragma unroll
        for (int it = 0; it < 2; it++) {
            int f = tid + 256 * it;          // 0..511
            int jj = f >> 4;
            int dd = (f & 15) * 4;
            *(float4*)&v_s[jj][dd] =
                *(const float4*)(g_qkv + (size_t)(b * SS + j0 + jj) * QKV_LD + 128 + dd);
        }
        // compute t, write probs in place, stage t transposed
#pragma unroll
        for (int it = 0; it < 2; it++) {
            int f = tid + 256 * it;          // 0..511 -> 64 rows x 8 float4
            int i = f >> 3;
            int j4 = (f & 7) * 4;
            float* p = sbase + (size_t)(i0 + i) * SS + j0 + j4;
            float4 s4 = *(float4*)p;
            float rdi = rdi_s[i];
            float t0 = s4.x * c_s[j0 + j4 + 0] * rdi;
            float t1 = s4.y * c_s[j0 + j4 + 1] * rdi;
            float t2 = s4.z * c_s[j0 + j4 + 2] * rdi;
            float t3 = s4.w * c_s[j0 + j4 + 3] * rdi;
            *(float4*)p = make_float4(t0, t1, t2, t3);
            t_s[j4 + 0][i] = t0; t_s[j4 + 1][i] = t1;
            t_s[j4 + 2][i] = t2; t_s[j4 + 3][i] = t3;
        }
        __syncthreads();
#pragma unroll
        for (int jj = 0; jj < 32; jj++) {
            float4 a  = *(float4*)&t_s[jj][ty * 4];
            float4 bv = *(float4*)&v_s[jj][tx * 4];
            float av[4] = {a.x, a.y, a.z, a.w};
            float bb[4] = {bv.x, bv.y, bv.z, bv.w};
#pragma unroll
            for (int r = 0; r < 4; r++)
#pragma unroll
                for (int c = 0; c < 4; c++)
                    acc[r][c] = fmaf(av[r], bb[c], acc[r][c]);
        }
        __syncthreads();
    }

#pragma unroll
    for (int r = 0; r < 4; r++) {
        *(float4*)(out + (size_t)(b * SS + i0 + ty * 4 + r) * DD + tx * 4) =
            make_float4(acc[r][0], acc[r][1], acc[r][2], acc[r][3]);
    }
}

// ----------------------------------------------------------------
extern "C" void kernel_launch(void* const* d_in, const int* in_sizes, int n_in,
                              void* d_out, int out_size)
{
    const float* x  = (const float*)d_in[0];
    const float* Wq = (const float*)d_in[1];
    const float* bq = (const float*)d_in[2];
    const float* Wk = (const float*)d_in[3];
    const float* bk = (const float*)d_in[4];
    const float* Wv = (const float*)d_in[5];
    const float* bv = (const float*)d_in[6];

    float* out   = (float*)d_out;                 // [B,S,64]
    float* probs = out + (size_t)BS * DD;         // [B,S,S]

    k0_zero<<<BS / 256, 256>>>();
    k1_proj<<<dim3(BS / 128, 3), 256>>>(x, Wq, bq, Wk, bk, Wv, bv);
    k2_norm<<<(BS * 3 * 32) / 256, 256>>>();
    k3_score<<<dim3(16, 16, BB), 256>>>(probs);
    k4_final<<<dim3(SS / 64, BB), 256>>>(out, probs);
}

// round 5
// speedup vs baseline: 1.0563x; 1.0563x over previous
#include <cuda_runtime.h>
#include <cuda_bf16.h>
#include <cstdint>
#include <math.h>

#define BB 8
#define SS 2048
#define HH 1024
#define DD 64
#define BS (BB*SS)      /* 16384 */
#define QKV_LD 192

#define CLIP_HI 0.9999998807907104f
#define PEXP (-65.5f)

// ---------------------------------------------------------------- scratch
__device__ float g_qkv[BS * QKV_LD];               // [row][ q(64) | k(64) | v(64) ]
__device__ float g_colsum[BS];                     // [B][S]
__device__ __nv_bfloat16 g_qsp[(size_t)BS * 128];  // [row][ q_hi(64) | q_lo(64) ]
__device__ __nv_bfloat16 g_ksp[(size_t)BS * 128];  // [row][ k_hi(64) | k_lo(64) ]

// ---------------------------------------------------------------- warp MMA helpers (arch-stable PTX)
__device__ __forceinline__ uint32_t smem_to_u32(const void* smem_ptr) {
    uint32_t addr;
    asm("{ .reg .u64 tmp; cvta.to.shared.u64 tmp, %1; cvt.u32.u64 %0, tmp; }"
        : "=r"(addr) : "l"(smem_ptr));
    return addr;
}

__device__ __forceinline__ void ldsm_x4(uint32_t* r, uint32_t addr) {
    asm volatile("ldmatrix.sync.aligned.m8n8.x4.shared.b16 {%0,%1,%2,%3}, [%4];"
        : "=r"(r[0]), "=r"(r[1]), "=r"(r[2]), "=r"(r[3]) : "r"(addr));
}
__device__ __forceinline__ void mma_bf16(float* d, const uint32_t* a, const uint32_t* b) {
    asm volatile(
        "mma.sync.aligned.m16n8k16.row.col.f32.bf16.bf16.f32 "
        "{%0,%1,%2,%3}, {%4,%5,%6,%7}, {%8,%9}, {%0,%1,%2,%3};"
        : "+f"(d[0]), "+f"(d[1]), "+f"(d[2]), "+f"(d[3])
        : "r"(a[0]), "r"(a[1]), "r"(a[2]), "r"(a[3]), "r"(b[0]), "r"(b[1]));
}

__device__ __forceinline__ float score_fn(float cosv) {
    cosv = fminf(fmaxf(cosv, -CLIP_HI), CLIP_HI);
    float gd = acosf(cosv);
    return __expf(PEXP * __logf(1.0f + gd));
}

// ---------------------------------------------------------------- K0: zero colsum
__global__ void k0_zero() {
    int i = blockIdx.x * blockDim.x + threadIdx.x;
    if (i < BS) g_colsum[i] = 0.0f;
}

// ---------------------------------------------------------------- K1: projections (unchanged, passing)
__global__ __launch_bounds__(256) void k1_proj(
    const float* __restrict__ x,
    const float* __restrict__ Wq, const float* __restrict__ bq,
    const float* __restrict__ Wk, const float* __restrict__ bk,
    const float* __restrict__ Wv, const float* __restrict__ bv)
{
    __shared__ float xs[32][128 + 4];
    __shared__ float ws[32][64 + 4];

    const int which = blockIdx.y;
    const float* W    = (which == 0) ? Wq : ((which == 1) ? Wk : Wv);
    const float* bias = (which == 0) ? bq : ((which == 1) ? bk : bv);
    const int m0 = blockIdx.x * 128;
    const int tid = threadIdx.x;
    const int tx = tid & 15, ty = tid >> 4;

    float acc[8][4];
#pragma unroll
    for (int r = 0; r < 8; r++)
#pragma unroll
        for (int c = 0; c < 4; c++) acc[r][c] = 0.0f;

    for (int k0 = 0; k0 < HH; k0 += 32) {
#pragma unroll
        for (int it = 0; it < 4; it++) {
            int f = tid + 256 * it;
            int row = f >> 3;
            int dd = (f & 7) * 4;
            float4 v = *(const float4*)(x + (size_t)(m0 + row) * HH + k0 + dd);
            xs[dd + 0][row] = v.x; xs[dd + 1][row] = v.y;
            xs[dd + 2][row] = v.z; xs[dd + 3][row] = v.w;
        }
#pragma unroll
        for (int it = 0; it < 2; it++) {
            int f = tid + 256 * it;
            int kr = f >> 4;
            int nn = (f & 15) * 4;
            *(float4*)&ws[kr][nn] = *(const float4*)(W + (size_t)(k0 + kr) * DD + nn);
        }
        __syncthreads();
#pragma unroll
        for (int kk = 0; kk < 32; kk++) {
            float4 a0 = *(float4*)&xs[kk][ty * 8];
            float4 a1 = *(float4*)&xs[kk][ty * 8 + 4];
            float4 b0 = *(float4*)&ws[kk][tx * 4];
            float a[8] = {a0.x, a0.y, a0.z, a0.w, a1.x, a1.y, a1.z, a1.w};
            float bb[4] = {b0.x, b0.y, b0.z, b0.w};
#pragma unroll
            for (int r = 0; r < 8; r++)
#pragma unroll
                for (int c = 0; c < 4; c++)
                    acc[r][c] = fmaf(a[r], bb[c], acc[r][c]);
        }
        __syncthreads();
    }

    float4 b4 = *(const float4*)(bias + tx * 4);
    float bb[4] = {b4.x, b4.y, b4.z, b4.w};
#pragma unroll
    for (int r = 0; r < 8; r++) {
        float4 o;
        o.x = acc[r][0] + bb[0]; o.y = acc[r][1] + bb[1];
        o.z = acc[r][2] + bb[2]; o.w = acc[r][3] + bb[3];
        *(float4*)(g_qkv + (size_t)(m0 + ty * 8 + r) * QKV_LD + which * 64 + tx * 4) = o;
    }
}

// ---------------------------------------------------------------- K2: L2 normalize + bf16 hi/lo split for q,k
__global__ void k2_norm() {
    int gw = (blockIdx.x * blockDim.x + threadIdx.x) >> 5;
    int lane = threadIdx.x & 31;
    if (gw >= BS * 3) return;
    int row = gw / 3;
    int mat = gw - row * 3;
    float* p = g_qkv + (size_t)row * QKV_LD + mat * 64;
    float2 v = *(float2*)(p + lane * 2);
    float ss = v.x * v.x + v.y * v.y;
#pragma unroll
    for (int o = 16; o; o >>= 1) ss += __shfl_xor_sync(0xFFFFFFFFu, ss, o);
    float inv = 1.0f / fmaxf(sqrtf(ss), 1e-12f);
    float a0 = v.x * inv, a1 = v.y * inv;
    if (mat == 2) {
        *(float2*)(p + lane * 2) = make_float2(a0, a1);
    } else {
        __nv_bfloat16* dst = (mat == 0 ? g_qsp : g_ksp) + (size_t)row * 128;
        __nv_bfloat16 h0 = __float2bfloat16(a0);
        __nv_bfloat16 h1 = __float2bfloat16(a1);
        __nv_bfloat16 l0 = __float2bfloat16(a0 - __bfloat162float(h0));
        __nv_bfloat16 l1 = __float2bfloat16(a1 - __bfloat162float(h1));
        *(__nv_bfloat162*)(dst + lane * 2)      = __halves2bfloat162(h0, h1);
        *(__nv_bfloat162*)(dst + 64 + lane * 2) = __halves2bfloat162(l0, l1);
    }
}

// ---------------------------------------------------------------- K3: QK^T via mma.sync bf16 4-split -> score, colsums
// Tile 128x128 per CTA; 8 warps; warp (w&3) -> 32-row band, (w>>2) -> 64-col band.
// A/B in smem as [128][136] bf16 (hi cols 0-63, lo cols 64-127).
// B loaded with NON-trans ldmatrix: smem is [n][k] row-major; b-frag wants
// consecutive-k per lane at fixed n, which non-trans delivers directly.
#define LDA 136
#define K3_SMEM (2 * 128 * LDA * 2)   /* 69632 bytes */

__global__ __launch_bounds__(256, 2) void k3_score(float* __restrict__ probs)
{
    extern __shared__ __nv_bfloat16 sm[];
    __nv_bfloat16* As = sm;
    __nv_bfloat16* Bs = sm + 128 * LDA;
    __shared__ float s_colsum[128];

    const int b  = blockIdx.z;
    const int m0 = blockIdx.y * 128;
    const int n0 = blockIdx.x * 128;
    const int tid = threadIdx.x;
    const int wid = tid >> 5, lane = tid & 31;

    if (tid < 128) s_colsum[tid] = 0.0f;

    // stage: 128 rows x 16 uint4 each matrix
    const uint4* qg = (const uint4*)(g_qsp + (size_t)(b * SS + m0) * 128);
    const uint4* kg = (const uint4*)(g_ksp + (size_t)(b * SS + n0) * 128);
#pragma unroll
    for (int it = 0; it < 8; it++) {
        int f = tid + 256 * it;              // 0..2047
        int row = f >> 4;
        int i = f & 15;
        *(uint4*)((char*)As + row * (LDA * 2) + i * 16) = qg[row * 16 + i];
        *(uint4*)((char*)Bs + row * (LDA * 2) + i * 16) = kg[row * 16 + i];
    }
    __syncthreads();

    // per-lane ldmatrix base addresses
    const uint32_t Ab = smem_to_u32(As), Bb = smem_to_u32(Bs);
    const int arow = lane & 15, ak8 = (lane >> 4) * 8;
    const uint32_t aBase = Ab + (uint32_t)(((wid & 3) * 32 + arow) * LDA + ak8) * 2;
    const int bn  = (lane & 7) + ((lane >> 4) << 3);
    const int bk8 = ((lane >> 3) & 1) * 8;
    const uint32_t bBase = Bb + (uint32_t)(((wid >> 2) * 64 + bn) * LDA + bk8) * 2;

    float acc[2][8][4];
#pragma unroll
    for (int mt = 0; mt < 2; mt++)
#pragma unroll
        for (int nb = 0; nb < 8; nb++)
#pragma unroll
            for (int i = 0; i < 4; i++) acc[mt][nb][i] = 0.0f;

    const int ai[4] = {0, 1, 0, 1};
    const int bi[4] = {0, 0, 1, 1};
#pragma unroll
    for (int seg = 0; seg < 4; seg++) {
        const int aoff = ai[seg] * 64, boff = bi[seg] * 64;
#pragma unroll
        for (int ks = 0; ks < 4; ks++) {
            const int k0 = ks * 16;
            uint32_t af[2][4];
            ldsm_x4(af[0], aBase + (uint32_t)(aoff + k0) * 2);
            ldsm_x4(af[1], aBase + (uint32_t)(16 * LDA + aoff + k0) * 2);
            uint32_t bf[4][4];
#pragma unroll
            for (int nt = 0; nt < 4; nt++)
                ldsm_x4(bf[nt], bBase + (uint32_t)(nt * 16 * LDA + boff + k0) * 2);
#pragma unroll
            for (int mt = 0; mt < 2; mt++)
#pragma unroll
                for (int nb = 0; nb < 8; nb++)
                    mma_bf16(acc[mt][nb], af[mt], &bf[nb >> 1][(nb & 1) * 2]);
        }
    }

    // epilogue: transform, store, column sums
    const int g = lane >> 2, cq = (lane & 3) * 2;
    const int colbase = n0 + (wid >> 2) * 64 + cq;
    float* pb = probs + (size_t)b * SS * SS;

    float colacc[16];
#pragma unroll
    for (int i = 0; i < 16; i++) colacc[i] = 0.0f;

#pragma unroll
    for (int mt = 0; mt < 2; mt++) {
#pragma unroll
        for (int h = 0; h < 2; h++) {
            const int row = m0 + (wid & 3) * 32 + mt * 16 + h * 8 + g;
            float* rp = pb + (size_t)row * SS + colbase;
#pragma unroll
            for (int nb = 0; nb < 8; nb++) {
                float x0 = score_fn(acc[mt][nb][h * 2 + 0]);
                float x1 = score_fn(acc[mt][nb][h * 2 + 1]);
                colacc[nb * 2 + 0] += x0;
                colacc[nb * 2 + 1] += x1;
                *(float2*)(rp + nb * 8) = make_float2(x0, x1);
            }
        }
    }

#pragma unroll
    for (int nb = 0; nb < 8; nb++) {
        float s0 = colacc[nb * 2], s1 = colacc[nb * 2 + 1];
#pragma unroll
        for (int o = 4; o <= 16; o <<= 1) {
            s0 += __shfl_xor_sync(0xFFFFFFFFu, s0, o);
            s1 += __shfl_xor_sync(0xFFFFFFFFu, s1, o);
        }
        if (lane < 4) {
            atomicAdd(&s_colsum[(wid >> 2) * 64 + nb * 8 + lane * 2 + 0], s0);
            atomicAdd(&s_colsum[(wid >> 2) * 64 + nb * 8 + lane * 2 + 1], s1);
        }
    }

    __syncthreads();
    if (tid < 128) atomicAdd(&g_colsum[b * SS + n0 + tid], s_colsum[tid]);
}

// ---------------------------------------------------------------- K4: finalize (unchanged, passing)
__global__ __launch_bounds__(256) void k4_final(float* __restrict__ out, float* __restrict__ probs)
{
    __shared__ float c_s[SS];
    __shared__ float t_s[32][64 + 4];
    __shared__ float v_s[32][64 + 4];
    __shared__ float rdi_s[64];
    __shared__ float red[64][4];

    const int b = blockIdx.y;
    const int i0 = blockIdx.x * 64;
    const int tid = threadIdx.x;
    float* sbase = probs + (size_t)b * SS * SS;

    for (int j = tid; j < SS; j += 256)
        c_s[j] = rsqrtf(g_colsum[b * SS + j]);
    __syncthreads();

    {
        int i = tid >> 2;
        int q = tid & 3;
        const float* rp = sbase + (size_t)(i0 + i) * SS + q * 512;
        const float* cp = c_s + q * 512;
        float sum = 0.0f;
        for (int j = 0; j < 512; j += 4) {
            float4 s4 = *(const float4*)(rp + j);
            sum += s4.x * cp[j] + s4.y * cp[j + 1] + s4.z * cp[j + 2] + s4.w * cp[j + 3];
        }
        red[i][q] = sum;
    }
    __syncthreads();
    if (tid < 64) {
        float d = red[tid][0] + red[tid][1] + red[tid][2] + red[tid][3];
        rdi_s[tid] = 1.0f / d;
    }
    __syncthreads();

    const int tx = tid & 15, ty = tid >> 4;
    float acc[4][4];
#pragma unroll
    for (int r = 0; r < 4; r++)
#pragma unroll
        for (int c = 0; c < 4; c++) acc[r][c] = 0.0f;

    for (int j0 = 0; j0 < SS; j0 += 32) {
#pragma unroll
        for (int it = 0; it < 2; it++) {
            int f = tid + 256 * it;
            int jj = f >> 4;
            int dd = (f & 15) * 4;
            *(float4*)&v_s[jj][dd] =
                *(const float4*)(g_qkv + (size_t)(b * SS + j0 + jj) * QKV_LD + 128 + dd);
        }
#pragma unroll
        for (int it = 0; it < 2; it++) {
            int f = tid + 256 * it;
            int i = f >> 3;
            int j4 = (f & 7) * 4;
            float* p = sbase + (size_t)(i0 + i) * SS + j0 + j4;
            float4 s4 = *(float4*)p;
            float rdi = rdi_s[i];
            float t0 = s4.x * c_s[j0 + j4 + 0] * rdi;
            float t1 = s4.y * c_s[j0 + j4 + 1] * rdi;
            float t2 = s4.z * c_s[j0 + j4 + 2] * rdi;
            float t3 = s4.w * c_s[j0 + j4 + 3] * rdi;
            *(float4*)p = make_float4(t0, t1, t2, t3);
            t_s[j4 + 0][i] = t0; t_s[j4 + 1][i] = t1;
            t_s[j4 + 2][i] = t2; t_s[j4 + 3][i] = t3;
        }
        __syncthreads();
#pragma unroll
        for (int jj = 0; jj < 32; jj++) {
            float4 a  = *(float4*)&t_s[jj][ty * 4];
            float4 bv = *(float4*)&v_s[jj][tx * 4];
            float av[4] = {a.x, a.y, a.z, a.w};
            float bb[4] = {bv.x, bv.y, bv.z, bv.w};
#pragma unroll
            for (int r = 0; r < 4; r++)
#pragma unroll
                for (int c = 0; c < 4; c++)
                    acc[r][c] = fmaf(av[r], bb[c], acc[r][c]);
        }
        __syncthreads();
    }

#pragma unroll
    for (int r = 0; r < 4; r++) {
        *(float4*)(out + (size_t)(b * SS + i0 + ty * 4 + r) * DD + tx * 4) =
            make_float4(acc[r][0], acc[r][1], acc[r][2], acc[r][3]);
    }
}

// ----------------------------------------------------------------
extern "C" void kernel_launch(void* const* d_in, const int* in_sizes, int n_in,
                              void* d_out, int out_size)
{
    const float* x  = (const float*)d_in[0];
    const float* Wq = (const float*)d_in[1];
    const float* bq = (const float*)d_in[2];
    const float* Wk = (const float*)d_in[3];
    const float* bk = (const float*)d_in[4];
    const float* Wv = (const float*)d_in[5];
    const float* bv = (const float*)d_in[6];

    float* out   = (float*)d_out;                 // [B,S,64]
    float* probs = out + (size_t)BS * DD;         // [B,S,S]

    cudaFuncSetAttribute(k3_score, cudaFuncAttributeMaxDynamicSharedMemorySize, K3_SMEM);

    k0_zero<<<BS / 256, 256>>>();
    k1_proj<<<dim3(BS / 128, 3), 256>>>(x, Wq, bq, Wk, bk, Wv, bv);
    k2_norm<<<(BS * 3 * 32) / 256, 256>>>();
    k3_score<<<dim3(16, 16, BB), 256, K3_SMEM>>>(probs);
    k4_final<<<dim3(SS / 64, BB), 256>>>(out, probs);
}